// round 1
// baseline (speedup 1.0000x reference)
#include <cuda_runtime.h>
#include <cstdint>

#define B_   8
#define S_   4096
#define D_   512
#define GK   6           // G + K
#define GN_  10          // grid knots
#define M_   (B_ * S_)   // 32768 rows
#define KA   (D_ + D_ * GK)  // 3584
#define LN_EPS 1e-5f

// ---------------- scratch (static device globals; no allocation) -------------
__device__ float g_A[(size_t)M_ * KA];   // [32768, 3584] activations (tf32-rounded fp32)
__device__ float g_W[(size_t)KA * D_];   // [3584, 512]  packed weights (tf32-rounded fp32)

// ---------------- helpers ----------------------------------------------------
__device__ __forceinline__ float to_tf32(float x) {
    uint32_t u;
    asm("cvt.rna.tf32.f32 %0, %1;" : "=r"(u) : "f"(x));
    return __uint_as_float(u);
}

__device__ __forceinline__ void cp_async16(void* smem_dst, const void* gsrc) {
    unsigned sa = (unsigned)__cvta_generic_to_shared(smem_dst);
    asm volatile("cp.async.cg.shared.global [%0], [%1], 16;" :: "r"(sa), "l"(gsrc) : "memory");
}
__device__ __forceinline__ void cp_commit() {
    asm volatile("cp.async.commit_group;" ::: "memory");
}
template<int N> __device__ __forceinline__ void cp_wait() {
    asm volatile("cp.async.wait_group %0;" :: "n"(N) : "memory");
}

// ---------------- kernel 1: LN + silu + b-spline bases -> g_A ----------------
// one block (256 threads) per row; thread t handles features 2t, 2t+1
__global__ void __launch_bounds__(256) act_kernel(
    const float* __restrict__ x,
    const float* __restrict__ lnw,
    const float* __restrict__ lnb,
    const float* __restrict__ grid)
{
    int row = blockIdx.x;
    int t   = threadIdx.x;
    const float2* xr2 = (const float2*)(x + (size_t)row * D_);
    float2 v = xr2[t];

    __shared__ float red[256];
    red[t] = v.x + v.y;
    __syncthreads();
    #pragma unroll
    for (int o = 128; o > 0; o >>= 1) {
        if (t < o) red[t] += red[t + o];
        __syncthreads();
    }
    float mu = red[0] * (1.0f / D_);
    __syncthreads();
    float d0 = v.x - mu, d1 = v.y - mu;
    red[t] = d0 * d0 + d1 * d1;
    __syncthreads();
    #pragma unroll
    for (int o = 128; o > 0; o >>= 1) {
        if (t < o) red[t] += red[t + o];
        __syncthreads();
    }
    float rstd = rsqrtf(red[0] * (1.0f / D_) + LN_EPS);

    float* Arow = g_A + (size_t)row * KA;
    float bases12[12];

    #pragma unroll
    for (int e = 0; e < 2; e++) {
        int feat = 2 * t + e;
        float xin = (e == 0) ? v.x : v.y;
        float xn = (xin - mu) * rstd * lnw[feat] + lnb[feat];
        // silu
        float sl = xn * (1.0f / (1.0f + expf(-xn)));
        Arow[feat] = to_tf32(sl);

        // Cox-de Boor, order 3, per-feature knots (GN_=10)
        const float* gk = grid + (size_t)feat * GN_;
        float g[GN_];
        #pragma unroll
        for (int j = 0; j < GN_; j++) g[j] = gk[j];
        float bs[GN_ - 1];
        #pragma unroll
        for (int j = 0; j < GN_ - 1; j++)
            bs[j] = (xn >= g[j] && xn < g[j + 1]) ? 1.0f : 0.0f;
        #pragma unroll
        for (int k = 1; k <= 3; k++) {
            #pragma unroll
            for (int j = 0; j < GN_ - 1 - 3; j++) {   // compute only what survives
                ;
            }
            #pragma unroll
            for (int j = 0; j + k < GN_ - 1; j++) {
                float left  = (xn - g[j]) / (g[j + k] - g[j]);
                float right = (g[j + k + 1] - xn) / (g[j + k + 1] - g[j + 1]);
                bs[j] = left * bs[j] + right * bs[j + 1];
            }
        }
        #pragma unroll
        for (int j = 0; j < GK; j++)
            bases12[e * GK + j] = to_tf32(bs[j]);
    }
    // 12 contiguous floats per thread -> 3 float4 stores (coalesced across warp)
    float4* dst = (float4*)(Arow + D_ + (size_t)12 * t);
    dst[0] = make_float4(bases12[0], bases12[1], bases12[2],  bases12[3]);
    dst[1] = make_float4(bases12[4], bases12[5], bases12[6],  bases12[7]);
    dst[2] = make_float4(bases12[8], bases12[9], bases12[10], bases12[11]);
}

// ---------------- kernel 2a: base weight copy (rows 0..511) ------------------
__global__ void __launch_bounds__(256) repack_base(const float* __restrict__ bw) {
    int idx = blockIdx.x * 256 + threadIdx.x;   // < 512*512
    g_W[idx] = to_tf32(bw[idx]);
}

// ---------------- kernel 2b: spline weight transpose (rows 512..3583) --------
// spline_weight [512 o][3072 k] -> g_W[512+k][o]
__global__ void __launch_bounds__(256) repack_spline(const float* __restrict__ sw) {
    __shared__ float tile[32][33];
    int k0 = blockIdx.x * 32;
    int o0 = blockIdx.y * 32;
    int tx = threadIdx.x & 31;
    int ty = threadIdx.x >> 5;     // 0..7
    #pragma unroll
    for (int i = 0; i < 32; i += 8)
        tile[ty + i][tx] = sw[(size_t)(o0 + ty + i) * (D_ * GK) + k0 + tx];
    __syncthreads();
    #pragma unroll
    for (int i = 0; i < 32; i += 8)
        g_W[(size_t)(D_ + k0 + ty + i) * D_ + o0 + tx] = to_tf32(tile[tx][ty + i]);
}

// ---------------- kernel 3: tf32 GEMM  C = A @ W + bias ----------------------
#define BM 128
#define BN 128
#define BK 16
#define AST 20    // padded smem stride for A tile (floats)
#define BST 136   // padded smem stride for B tile (floats)

__global__ void __launch_bounds__(256) gemm_kernel(
    const float* __restrict__ bias, float* __restrict__ out)
{
    __shared__ float sA[2][BM * AST];
    __shared__ float sB[2][BK * BST];

    int tid  = threadIdx.x;
    int bn   = blockIdx.x;   // 0..3
    int bm   = blockIdx.y;   // 0..255
    int warp = tid >> 5, lane = tid & 31;
    int wm = warp >> 1;      // 0..3 : 32 rows each
    int wn = warp & 1;       // 0..1 : 64 cols each
    int lg = lane >> 2;      // groupID 0..7
    int lt = lane & 3;       // threadID in group

    const float* Ab = g_A + (size_t)(bm * BM) * KA;
    const float* Bb = g_W + bn * BN;

    // load mapping
    int arow = tid >> 1;                 // 0..127
    int acol = (tid & 1) * 8;            // 0 or 8 (two float4 chunks)
    float acc[2][8][4];
    #pragma unroll
    for (int i = 0; i < 2; i++)
        #pragma unroll
        for (int j = 0; j < 8; j++)
            #pragma unroll
            for (int c = 0; c < 4; c++) acc[i][j][c] = 0.0f;

    const int NT = KA / BK;   // 224

    // prologue: tile 0
    {
        const float* Asrc = Ab + (size_t)arow * KA + acol;
        cp_async16(&sA[0][arow * AST + acol],     Asrc);
        cp_async16(&sA[0][arow * AST + acol + 4], Asrc + 4);
        #pragma unroll
        for (int p = 0; p < 2; p++) {
            int idx = tid + p * 256;
            int br = idx >> 5, bc = (idx & 31) * 4;
            cp_async16(&sB[0][br * BST + bc], Bb + (size_t)br * D_ + bc);
        }
        cp_commit();
    }

    for (int kt = 0; kt < NT; kt++) {
        int buf = kt & 1;
        if (kt + 1 < NT) {
            int nb = buf ^ 1;
            const float* Asrc = Ab + (size_t)arow * KA + (kt + 1) * BK + acol;
            cp_async16(&sA[nb][arow * AST + acol],     Asrc);
            cp_async16(&sA[nb][arow * AST + acol + 4], Asrc + 4);
            #pragma unroll
            for (int p = 0; p < 2; p++) {
                int idx = tid + p * 256;
                int br = idx >> 5, bc = (idx & 31) * 4;
                cp_async16(&sB[nb][br * BST + bc],
                           Bb + (size_t)((kt + 1) * BK + br) * D_ + bc);
            }
            cp_commit();
            cp_wait<1>();
        } else {
            cp_wait<0>();
        }
        __syncthreads();

        const float* As = sA[buf];
        const float* Bs = sB[buf];
        #pragma unroll
        for (int ks = 0; ks < 2; ks++) {
            int k0 = ks * 8;
            uint32_t a[2][4];
            #pragma unroll
            for (int mt = 0; mt < 2; mt++) {
                int r = wm * 32 + mt * 16 + lg;
                a[mt][0] = __float_as_uint(As[r * AST + k0 + lt]);
                a[mt][1] = __float_as_uint(As[(r + 8) * AST + k0 + lt]);
                a[mt][2] = __float_as_uint(As[r * AST + k0 + lt + 4]);
                a[mt][3] = __float_as_uint(As[(r + 8) * AST + k0 + lt + 4]);
            }
            #pragma unroll
            for (int nt = 0; nt < 8; nt++) {
                int c = wn * 64 + nt * 8 + lg;
                uint32_t b0 = __float_as_uint(Bs[(k0 + lt) * BST + c]);
                uint32_t b1 = __float_as_uint(Bs[(k0 + lt + 4) * BST + c]);
                #pragma unroll
                for (int mt = 0; mt < 2; mt++) {
                    asm volatile(
                        "mma.sync.aligned.m16n8k8.row.col.f32.tf32.tf32.f32 "
                        "{%0,%1,%2,%3}, {%4,%5,%6,%7}, {%8,%9}, {%0,%1,%2,%3};"
                        : "+f"(acc[mt][nt][0]), "+f"(acc[mt][nt][1]),
                          "+f"(acc[mt][nt][2]), "+f"(acc[mt][nt][3])
                        : "r"(a[mt][0]), "r"(a[mt][1]), "r"(a[mt][2]), "r"(a[mt][3]),
                          "r"(b0), "r"(b1));
                }
            }
        }
        __syncthreads();
    }

    // epilogue: C += bias, write out
    #pragma unroll
    for (int mt = 0; mt < 2; mt++) {
        int row = bm * BM + wm * 32 + mt * 16 + lg;
        #pragma unroll
        for (int nt = 0; nt < 8; nt++) {
            int col = bn * BN + wn * 64 + nt * 8 + 2 * lt;
            float b0 = bias[col], b1 = bias[col + 1];
            out[(size_t)row * D_ + col]           = acc[mt][nt][0] + b0;
            out[(size_t)row * D_ + col + 1]       = acc[mt][nt][1] + b1;
            out[(size_t)(row + 8) * D_ + col]     = acc[mt][nt][2] + b0;
            out[(size_t)(row + 8) * D_ + col + 1] = acc[mt][nt][3] + b1;
        }
    }
}

// ---------------- launch ------------------------------------------------------
extern "C" void kernel_launch(void* const* d_in, const int* in_sizes, int n_in,
                              void* d_out, int out_size) {
    const float* x      = (const float*)d_in[0];  // [8,4096,512]
    const float* lnw    = (const float*)d_in[1];  // [512]
    const float* lnb    = (const float*)d_in[2];  // [512]
    const float* bw     = (const float*)d_in[3];  // [512,512]  (in,out)
    const float* bbias  = (const float*)d_in[4];  // [512]
    const float* sw     = (const float*)d_in[5];  // [512, 3072] (out, in*6)
    const float* grid   = (const float*)d_in[6];  // [512, 10]
    float* out = (float*)d_out;

    // pack weights
    repack_base<<<(D_ * D_) / 256, 256>>>(bw);
    {
        dim3 g((D_ * GK) / 32, D_ / 32);
        repack_spline<<<g, 256>>>(sw);
    }
    // activations
    act_kernel<<<M_, 256>>>(x, lnw, lnb, grid);
    // fused GEMM (base + spline) with bias
    {
        dim3 g(D_ / BN, M_ / BM);
        gemm_kernel<<<g, 256>>>(bbias, out);
    }
}

// round 15
// speedup vs baseline: 2.0143x; 2.0143x over previous
#include <cuda_runtime.h>
#include <cuda_fp16.h>
#include <cstdint>

#define NB    8
#define NS    4096
#define ND    512
#define NGK   6
#define NGN   10
#define NM    (NB * NS)        // 32768
#define NKA   (ND + ND * NGK)  // 3584
#define LN_EPS 1e-5f

// ---------------- scratch (static device globals; no allocation) -------------
__device__ __half g_A [(size_t)NM * NKA];   // [32768, 3584] activations (fp16)
__device__ __half g_WT[(size_t)ND * NKA];   // [512, 3584]   W^T out-major (fp16)
__device__ float  g_inv[ND * 24];           // per-feature inverse knot spacings

// ---------------- helpers ----------------------------------------------------
__device__ __forceinline__ void cp_async16(void* dst, const void* src) {
    uint32_t d = (uint32_t)__cvta_generic_to_shared(dst);
    asm volatile("cp.async.cg.shared.global [%0], [%1], 16;" :: "r"(d), "l"(src) : "memory");
}
__device__ __forceinline__ void cp_commit() {
    asm volatile("cp.async.commit_group;" ::: "memory");
}
template<int N> __device__ __forceinline__ void cp_wait() {
    asm volatile("cp.async.wait_group %0;" :: "n"(N) : "memory");
}

// ---------------- kernel 0: inverse knot spacings ----------------------------
__global__ void prep_inv(const float* __restrict__ grid) {
    int f = threadIdx.x;            // 512 threads
    const float* gp = grid + f * NGN;
    float g[10];
    #pragma unroll
    for (int j = 0; j < 10; j++) g[j] = gp[j];
    float* o = g_inv + f * 24;
    #pragma unroll
    for (int j = 0; j < 9; j++) o[j]      = 1.0f / (g[j + 1] - g[j]);
    #pragma unroll
    for (int j = 0; j < 8; j++) o[9 + j]  = 1.0f / (g[j + 2] - g[j]);
    #pragma unroll
    for (int j = 0; j < 7; j++) o[17 + j] = 1.0f / (g[j + 3] - g[j]);
}

// ---------------- kernel 1: LN + silu + b-splines -> g_A (fp16) --------------
// block = 512 threads, 16 rows. Phase1: warp-per-row LN stats. Phase2: thread-per-feature.
__global__ void __launch_bounds__(512) act_kernel(
    const float* __restrict__ x, const float* __restrict__ lnw,
    const float* __restrict__ lnb, const float* __restrict__ grid)
{
    __shared__ float s_mu[16], s_rs[16];
    int tid = threadIdx.x, warp = tid >> 5, lane = tid & 31;
    int row0 = blockIdx.x * 16;
    {
        const float4* xr = (const float4*)(x + (size_t)(row0 + warp) * ND);
        float4 v[4];
        float s = 0.f;
        #pragma unroll
        for (int i = 0; i < 4; i++) {
            v[i] = xr[lane * 4 + i];
            s += v[i].x + v[i].y + v[i].z + v[i].w;
        }
        #pragma unroll
        for (int o = 16; o > 0; o >>= 1) s += __shfl_xor_sync(0xffffffffu, s, o);
        float mu = s * (1.f / ND);
        float vs = 0.f;
        #pragma unroll
        for (int i = 0; i < 4; i++) {
            float a = v[i].x - mu, b = v[i].y - mu, c = v[i].z - mu, d = v[i].w - mu;
            vs += a * a + b * b + c * c + d * d;
        }
        #pragma unroll
        for (int o = 16; o > 0; o >>= 1) vs += __shfl_xor_sync(0xffffffffu, vs, o);
        if (lane == 0) { s_mu[warp] = mu; s_rs[warp] = rsqrtf(vs * (1.f / ND) + LN_EPS); }
    }
    __syncthreads();

    int f = tid;
    float w = lnw[f], b = lnb[f];
    float g[10];
    #pragma unroll
    for (int j = 0; j < 10; j++) g[j] = grid[f * NGN + j];
    const float* ip = g_inv + f * 24;
    float i1[9], i2[8], i3[7];
    #pragma unroll
    for (int j = 0; j < 9; j++) i1[j] = ip[j];
    #pragma unroll
    for (int j = 0; j < 8; j++) i2[j] = ip[9 + j];
    #pragma unroll
    for (int j = 0; j < 7; j++) i3[j] = ip[17 + j];

    for (int r = 0; r < 16; r++) {
        float xv = x[(size_t)(row0 + r) * ND + f];
        float xn = (xv - s_mu[r]) * s_rs[r] * w + b;
        __half* Arow = g_A + (size_t)(row0 + r) * NKA;
        float sig = 1.f / (1.f + __expf(-xn));
        Arow[f] = __float2half_rn(xn * sig);
        float bs[9];
        #pragma unroll
        for (int j = 0; j < 9; j++) bs[j] = (xn >= g[j] && xn < g[j + 1]) ? 1.f : 0.f;
        #pragma unroll
        for (int j = 0; j < 8; j++)
            bs[j] = (xn - g[j]) * i1[j] * bs[j] + (g[j + 2] - xn) * i1[j + 1] * bs[j + 1];
        #pragma unroll
        for (int j = 0; j < 7; j++)
            bs[j] = (xn - g[j]) * i2[j] * bs[j] + (g[j + 3] - xn) * i2[j + 1] * bs[j + 1];
        #pragma unroll
        for (int j = 0; j < 6; j++)
            bs[j] = (xn - g[j]) * i3[j] * bs[j] + (g[j + 4] - xn) * i3[j + 1] * bs[j + 1];
        __half2 p0 = __floats2half2_rn(bs[0], bs[1]);
        __half2 p1 = __floats2half2_rn(bs[2], bs[3]);
        __half2 p2 = __floats2half2_rn(bs[4], bs[5]);
        uint32_t* dst = (uint32_t*)(Arow + ND + f * 6);   // byte off 1024+12f, 4B aligned
        dst[0] = *(uint32_t*)&p0;
        dst[1] = *(uint32_t*)&p1;
        dst[2] = *(uint32_t*)&p2;
    }
}

// ---------------- kernel 2a: base weight transpose  g_WT[o][i] = bw[i][o] ----
__global__ void __launch_bounds__(256) repack_baseT(const float* __restrict__ bw) {
    __shared__ float tile[32][33];
    int i0 = blockIdx.x * 32, o0 = blockIdx.y * 32;
    int tx = threadIdx.x & 31, ty = threadIdx.x >> 5;
    #pragma unroll
    for (int r = 0; r < 32; r += 8)
        tile[ty + r][tx] = bw[(size_t)(i0 + ty + r) * ND + o0 + tx];
    __syncthreads();
    #pragma unroll
    for (int r = 0; r < 32; r += 8)
        g_WT[(size_t)(o0 + ty + r) * NKA + i0 + tx] = __float2half_rn(tile[tx][ty + r]);
}

// ---------------- kernel 2b: spline weight copy  g_WT[o][512+k] = sw[o][k] ---
__global__ void __launch_bounds__(256) repack_splineT(const float* __restrict__ sw) {
    int fidx = blockIdx.x * 256 + threadIdx.x;   // < 512*768
    int o  = fidx / 768;
    int j4 = fidx % 768;
    float4 v = ((const float4*)sw)[(size_t)o * 768 + j4];
    __half2 h0 = __floats2half2_rn(v.x, v.y);
    __half2 h1 = __floats2half2_rn(v.z, v.w);
    uint2 u;
    u.x = *(uint32_t*)&h0;
    u.y = *(uint32_t*)&h1;
    *(uint2*)(g_WT + (size_t)o * NKA + ND + j4 * 4) = u;   // 8B aligned
}

// ---------------- kernel 3: fp16 mma.sync GEMM  C = A @ W^T + bias -----------
#define BM 128
#define BN 128
#define BK 32                     // halfs per k-tile: 2 x k16 MMA steps
#define STG 4
#define NT (NKA / BK)             // 112
#define ROWB 80                   // padded row stride in BYTES (32 halfs + 8 pad)
#define A_BYTES (BM * ROWB)       // 10240
#define B_BYTES (BN * ROWB)       // 10240
#define STG_BYTES (A_BYTES + B_BYTES)   // 20480
#define GSMEM (STG * STG_BYTES)   // 81920

__global__ void __launch_bounds__(256, 2) gemm_kernel(
    const float* __restrict__ bias, float* __restrict__ out)
{
    extern __shared__ __align__(128) char smem[];
    int tid = threadIdx.x, warp = tid >> 5, lane = tid & 31;
    int wm = warp >> 1;           // 0..3 : 32-row strips
    int wn = warp & 1;            // 0..1 : 64-col strips
    int lg = lane >> 2;           // groupID 0..7
    int lt = lane & 3;            // thread-in-group
    int bn = blockIdx.x, bm = blockIdx.y;

    // cp.async mapping: thread -> (row, 32B half-row chunk); same for A and B
    int ldrow = tid >> 1;                  // 0..127
    int ldcol = (tid & 1) * 16;            // half index 0 or 16

    const __half* Asrc0 = g_A  + (size_t)(bm * BM + ldrow) * NKA + ldcol;
    const __half* Bsrc0 = g_WT + (size_t)(bn * BN + ldrow) * NKA + ldcol;
    char* sArow = smem + ldrow * ROWB + ldcol * 2;   // + stage offset later

    auto load_stage = [&](int s, int kt) {
        char* sA = sArow + s * STG_BYTES;
        char* sB = sA + A_BYTES;
        const __half* as = Asrc0 + kt * BK;
        const __half* bs = Bsrc0 + kt * BK;
        cp_async16(sA,      as);
        cp_async16(sA + 16, as + 8);
        cp_async16(sB,      bs);
        cp_async16(sB + 16, bs + 8);
    };

    float acc[2][8][4];
    #pragma unroll
    for (int i = 0; i < 2; i++)
        #pragma unroll
        for (int j = 0; j < 8; j++)
            #pragma unroll
            for (int c = 0; c < 4; c++) acc[i][j][c] = 0.0f;

    // prologue: stages 0..2
    #pragma unroll
    for (int p = 0; p < STG - 1; p++) { load_stage(p, p); cp_commit(); }

    for (int kt = 0; kt < NT; kt++) {
        int s = kt & (STG - 1);
        cp_wait<STG - 2>();
        __syncthreads();

        const char* sA = smem + s * STG_BYTES;
        const char* sB = sA + A_BYTES;

        #pragma unroll
        for (int ks = 0; ks < 2; ks++) {
            int k0 = ks * 16;   // half index within row
            uint32_t a[2][4];
            #pragma unroll
            for (int mt = 0; mt < 2; mt++) {
                int r = wm * 32 + mt * 16 + lg;
                a[mt][0] = *(const uint32_t*)(sA + r * ROWB       + (k0 + 2 * lt) * 2);
                a[mt][1] = *(const uint32_t*)(sA + (r + 8) * ROWB + (k0 + 2 * lt) * 2);
                a[mt][2] = *(const uint32_t*)(sA + r * ROWB       + (k0 + 8 + 2 * lt) * 2);
                a[mt][3] = *(const uint32_t*)(sA + (r + 8) * ROWB + (k0 + 8 + 2 * lt) * 2);
            }
            #pragma unroll
            for (int nt = 0; nt < 8; nt++) {
                int n = wn * 64 + nt * 8 + lg;
                uint32_t b0 = *(const uint32_t*)(sB + n * ROWB + (k0 + 2 * lt) * 2);
                uint32_t b1 = *(const uint32_t*)(sB + n * ROWB + (k0 + 8 + 2 * lt) * 2);
                #pragma unroll
                for (int mt = 0; mt < 2; mt++) {
                    asm volatile(
                        "mma.sync.aligned.m16n8k16.row.col.f32.f16.f16.f32 "
                        "{%0,%1,%2,%3}, {%4,%5,%6,%7}, {%8,%9}, {%0,%1,%2,%3};"
                        : "+f"(acc[mt][nt][0]), "+f"(acc[mt][nt][1]),
                          "+f"(acc[mt][nt][2]), "+f"(acc[mt][nt][3])
                        : "r"(a[mt][0]), "r"(a[mt][1]), "r"(a[mt][2]), "r"(a[mt][3]),
                          "r"(b0), "r"(b1));
                }
            }
        }
        __syncthreads();

        int lt_kt = kt + STG - 1;
        if (lt_kt < NT) load_stage(lt_kt & (STG - 1), lt_kt);
        cp_commit();   // one group per iteration (empty in tail)
    }

    // epilogue: C += bias
    #pragma unroll
    for (int mt = 0; mt < 2; mt++) {
        int row = bm * BM + wm * 32 + mt * 16 + lg;
        #pragma unroll
        for (int nt = 0; nt < 8; nt++) {
            int col = bn * BN + wn * 64 + nt * 8 + 2 * lt;
            float b0 = bias[col], b1 = bias[col + 1];
            out[(size_t)row * ND + col]           = acc[mt][nt][0] + b0;
            out[(size_t)row * ND + col + 1]       = acc[mt][nt][1] + b1;
            out[(size_t)(row + 8) * ND + col]     = acc[mt][nt][2] + b0;
            out[(size_t)(row + 8) * ND + col + 1] = acc[mt][nt][3] + b1;
        }
    }
}

// ---------------- launch ------------------------------------------------------
extern "C" void kernel_launch(void* const* d_in, const int* in_sizes, int n_in,
                              void* d_out, int out_size) {
    const float* x     = (const float*)d_in[0];  // [8,4096,512]
    const float* lnw   = (const float*)d_in[1];  // [512]
    const float* lnb   = (const float*)d_in[2];  // [512]
    const float* bw    = (const float*)d_in[3];  // [512,512] (in,out)
    const float* bbias = (const float*)d_in[4];  // [512]
    const float* swp   = (const float*)d_in[5];  // [512,3072] (out, k)
    const float* grid  = (const float*)d_in[6];  // [512,10]
    float* out = (float*)d_out;

    cudaFuncSetAttribute(gemm_kernel, cudaFuncAttributeMaxDynamicSharedMemorySize, GSMEM);

    prep_inv<<<1, 512>>>(grid);
    repack_baseT<<<dim3(16, 16), 256>>>(bw);
    repack_splineT<<<1536, 256>>>(swp);
    act_kernel<<<NM / 16, 512>>>(x, lnw, lnb, grid);
    gemm_kernel<<<dim3(ND / BN, NM / BM), 256, GSMEM>>>(bbias, out);
}